// round 17
// baseline (speedup 1.0000x reference)
#include <cuda_runtime.h>

#define N_POINTS 1000000
#define N_BASIS  64
#define DEG      3
#define NKNOT    68             // N_BASIS + DEG + 1
#define NINTERVAL (NKNOT - 1)   // 67
#define TPB 256
#define NVEC (N_POINTS / 4)     // 250000 float4 units
#define NBLOCKS ((NVEC + TPB - 1) / TPB)   // 977 — single wave on 148 SMs

// B-spline evaluation collapsed to a piecewise cubic:
// On each knot interval j, sum_i coefs[i]*B_i(x) is a single cubic in
// g = 67x - j (degree-3 spline, uniform knots, linear coef dot). Each block
// rebuilds the 67-entry cubic-coefficient table in smem (threads 0..66,
// exact reference recursion semantics incl. unclamped-knot truncation),
// overlapped with the front-issued x loads. Then each thread evaluates one
// float4 of points: 1 LDG.128 -> 4x (LDS.128 + 3 FFMA Horner) -> 1 STG.128.
// x ~ uniform[0,1) => f = 67x in [0,67), j = floor(f) in [0,66]: no clamps.
__global__ void __launch_bounds__(TPB)
bspline_fused_kernel(const float* __restrict__ x,
                     const float* __restrict__ coefs,
                     float* __restrict__ out)
{
    __shared__ float4 tab[NINTERVAL];

    const int tid    = threadIdx.x;
    const int vecIdx = blockIdx.x * TPB + tid;      // float4 unit
    const bool act   = vecIdx < NVEC;

    // Front-issue the x load (streaming) — overlaps the table build below.
    float4 xv;
    if (act) xv = __ldcs(reinterpret_cast<const float4*>(x) + vecIdx);

    // ---- Per-block table build: threads 0..66, interval j = tid ----------
    if (tid < NINTERVAL) {
        const int j = tid;
        float ys[4];
        #pragma unroll
        for (int s = 0; s < 4; ++s) {
            const float g = (float)s * (1.0f / 3.0f);
            // Piece polynomial of interval j: degree-0 seed B0_j = 1.
            float B[4] = {0.f, 0.f, 0.f, 1.f};      // d <-> i = j-3+d
            #pragma unroll
            for (int k = 1; k <= DEG; ++k) {
                const float invk = 1.0f / (float)k;
                float nB[4];
                #pragma unroll
                for (int d = 0; d < 4; ++d) {
                    // reference truncation: exists iff 0 <= i <= 66-k
                    const bool ok = (j >= 3 - d) && (j <= (NKNOT - 2) + 3 - k - d);
                    const float a = (g + (float)(3 - d)) * invk;
                    const float b = ((float)(d + k - 2) - g) * invk;
                    const float right = (d < 3) ? B[d + 1] : 0.f;
                    nB[d] = ok ? (a * B[d] + b * right) : 0.f;
                }
                #pragma unroll
                for (int d = 0; d < 4; ++d) B[d] = nB[d];
            }
            float y = 0.f;
            #pragma unroll
            for (int d = 0; d < 4; ++d) {
                const int idx = min(max(j - 3 + d, 0), N_BASIS - 1);
                y += coefs[idx] * B[d];             // invalid d -> B==0
            }
            ys[s] = y;
        }
        // Newton forward differences on u = 3g in {0,1,2,3}
        const float d1 = ys[1] - ys[0];
        const float d2 = ys[2] - 2.f * ys[1] + ys[0];
        const float d3 = ys[3] - 3.f * ys[2] + 3.f * ys[1] - ys[0];
        const float b1 = d1 - 0.5f * d2 + d3 * (1.f / 3.f);
        const float b2 = 0.5f * (d2 - d3);
        const float b3 = d3 * (1.f / 6.f);
        tab[j] = make_float4(ys[0], 3.f * b1, 9.f * b2, 27.f * b3);
    }
    __syncthreads();

    if (!act) return;

    float xs[4] = {xv.x, xv.y, xv.z, xv.w};
    float res[4];
    #pragma unroll
    for (int p = 0; p < 4; ++p) {
        const float f  = xs[p] * (float)NINTERVAL;  // 67*x in [0, 67)
        const float jf = floorf(f);
        const int   j  = (int)jf;                   // 0..66, no clamp needed
        const float g  = f - jf;                    // exact in [0,1)
        const float4 a = tab[j];
        res[p] = fmaf(fmaf(fmaf(a.w, g, a.z), g, a.y), g, a.x);
    }

    __stcs(reinterpret_cast<float4*>(out) + vecIdx,
           make_float4(res[0], res[1], res[2], res[3]));
}

extern "C" void kernel_launch(void* const* d_in, const int* in_sizes, int n_in,
                              void* d_out, int out_size)
{
    const float* x     = (const float*)d_in[0];
    const float* coefs = (const float*)d_in[2];
    float* out = (float*)d_out;

    bspline_fused_kernel<<<NBLOCKS, TPB>>>(x, coefs, out);
}